// round 13
// baseline (speedup 1.0000x reference)
#include <cuda_runtime.h>
#include <cuda_fp16.h>
#include <cstdint>

// Problem constants
#define NROWS 65536
#define DD    512
#define NL    8
#define HH    256
#define HALFD 256

// Tiling: MT=64 rows/CTA, 8 warps = 2(M) x 4(N), warp tile 32x64 for ALL GEMMs.
// o-state lives in gmem (the output buffer) => smem ~101KB => 2 CTAs/SM.
#define MT      64
#define THREADS 256
#define NCTAS   (NROWS / MT)   // 1024
#define LDE     264            // halfs, leading dim of e tile
#define LDH     520            // halfs, leading dim of h tile (512 cols + pad)

// Packed fp16 weights, kpair-fused mma-B-fragment order:
// [layer][mat 4][kpair 8][ntile 32][lane 32] as uint4:
//   .x,.y = kstep 2*kp fragments ; .z,.w = kstep 2*kp+1 fragments
__device__ uint4 g_wpack[NL * 4 * 8 * 32 * 32];

__global__ void pack_w(const float* __restrict__ Ws1, const float* __restrict__ Ws2,
                       const float* __restrict__ Wt1, const float* __restrict__ Wt2)
{
    int idx = blockIdx.x * blockDim.x + threadIdx.x;
    if (idx >= NL * 4 * 8 * 32 * 32) return;
    int lane  = idx & 31;
    int nt    = (idx >> 5) & 31;
    int kp    = (idx >> 10) & 7;
    int mat   = (idx >> 13) & 3;
    int layer = idx >> 15;
    const float* W = (mat == 0) ? Ws1 : (mat == 1) ? Ws2 : (mat == 2) ? Wt1 : Wt2;
    W += (size_t)layer * HH * HALFD;   // every matrix is 256x256 [K][N] row-major
    int n  = nt * 8 + (lane >> 2);
    int k0 = kp * 32 + (lane & 3) * 2;
    __half2 p0 = __floats2half2_rn(W[(k0     ) * 256 + n], W[(k0 +  1) * 256 + n]);
    __half2 p1 = __floats2half2_rn(W[(k0 +  8) * 256 + n], W[(k0 +  9) * 256 + n]);
    __half2 p2 = __floats2half2_rn(W[(k0 + 16) * 256 + n], W[(k0 + 17) * 256 + n]);
    __half2 p3 = __floats2half2_rn(W[(k0 + 24) * 256 + n], W[(k0 + 25) * 256 + n]);
    uint4 v;
    v.x = *reinterpret_cast<uint32_t*>(&p0);
    v.y = *reinterpret_cast<uint32_t*>(&p1);
    v.z = *reinterpret_cast<uint32_t*>(&p2);
    v.w = *reinterpret_cast<uint32_t*>(&p3);
    g_wpack[idx] = v;
}

__device__ __forceinline__ void mma16816(float c[4], const uint32_t a[4], uint32_t b0, uint32_t b1)
{
    asm volatile(
        "mma.sync.aligned.m16n8k16.row.col.f32.f16.f16.f32 "
        "{%0,%1,%2,%3},{%4,%5,%6,%7},{%8,%9},{%0,%1,%2,%3};\n"
        : "+f"(c[0]), "+f"(c[1]), "+f"(c[2]), "+f"(c[3])
        : "r"(a[0]), "r"(a[1]), "r"(a[2]), "r"(a[3]), "r"(b0), "r"(b1));
}

__device__ __forceinline__ void ldmA(uint32_t a[4], uint32_t addr)
{
    asm volatile(
        "ldmatrix.sync.aligned.m8n8.x4.shared.b16 {%0,%1,%2,%3},[%4];\n"
        : "=r"(a[0]), "=r"(a[1]), "=r"(a[2]), "=r"(a[3])
        : "r"(addr));
}

__device__ __forceinline__ float tanh_acc(float x)
{
    x = fminf(fmaxf(x, -15.f), 15.f);
    float e2 = __expf(2.f * x);
    return __fdividef(e2 - 1.f, e2 + 1.f);
}

// One GEMM: warp tile 32x64, K=256. A via ldmatrix from smem (a0 = per-lane base,
// mstride = byte offset of the +16-row half). B from gmem fragments (wlane).
__device__ __forceinline__ void gemm64(uint32_t a0, uint32_t mstride,
                                       const uint4* __restrict__ wlane,
                                       float acc[2][8][4])
{
    #pragma unroll
    for (int mt = 0; mt < 2; mt++)
        #pragma unroll
        for (int j = 0; j < 8; j++)
            #pragma unroll
            for (int q = 0; q < 4; q++) acc[mt][j][q] = 0.f;

    #pragma unroll
    for (int kp = 0; kp < 8; kp++) {
        uint4 b[8];
        #pragma unroll
        for (int j = 0; j < 8; j++) b[j] = wlane[kp * 1024 + j * 32];
        uint32_t a[2][4];
        ldmA(a[0], a0 + (2 * kp) * 32);
        ldmA(a[1], a0 + (2 * kp) * 32 + mstride);
        #pragma unroll
        for (int mt = 0; mt < 2; mt++)
            #pragma unroll
            for (int j = 0; j < 8; j++)
                mma16816(acc[mt][j], a[mt], b[j].x, b[j].y);
        ldmA(a[0], a0 + (2 * kp + 1) * 32);
        ldmA(a[1], a0 + (2 * kp + 1) * 32 + mstride);
        #pragma unroll
        for (int mt = 0; mt < 2; mt++)
            #pragma unroll
            for (int j = 0; j < 8; j++)
                mma16816(acc[mt][j], a[mt], b[j].z, b[j].w);
    }
}

// SMEM layout (bytes): e + h + lj ~= 101.4KB -> 2 CTAs/SM
#define SM_E   0
#define SM_H   (MT * LDE * 2)                 // 33792
#define SM_LJ  (SM_H + MT * LDH * 2)          // 100352
#define SM_TOT (SM_LJ + MT * 4 * 4)           // 101376

__global__ void __launch_bounds__(THREADS, 2) nvp_main(
    const float* __restrict__ z,
    const float* __restrict__ bs1, const float* __restrict__ bs2,
    const float* __restrict__ bt1, const float* __restrict__ bt2,
    float* __restrict__ out)
{
    extern __shared__ char smraw[];
    __half* e_s  = reinterpret_cast<__half*>(smraw + SM_E);
    __half* h_s  = reinterpret_cast<__half*>(smraw + SM_H);
    float*  lj_s = reinterpret_cast<float*>(smraw + SM_LJ);

    const int tid  = threadIdx.x;
    const int row0 = blockIdx.x * MT;

    // Load z: even cols -> e (f16 smem) + identity half of out; odd cols -> o (gmem out).
    for (int idx = tid; idx < MT * 256; idx += THREADS) {
        int r = idx >> 8, c = idx & 255;
        float2 p = reinterpret_cast<const float2*>(z + (size_t)(row0 + r) * DD)[c];
        e_s[r * LDE + c] = __float2half_rn(p.x);
        out[(size_t)(row0 + r) * DD + c]       = p.x;
        out[(size_t)(row0 + r) * DD + 256 + c] = p.y;
    }
    __syncthreads();

    const int warp = tid >> 5, lane = tid & 31;
    const int wm = warp & 1, wn = warp >> 1;       // 2(M) x 4(N); warp tile 32x64
    const int g = lane >> 2, tg = lane & 3;
    const int mat = lane >> 3, within = lane & 7;
    const int rowoff = ((mat & 1) << 3) + within;  // ldmatrix per-lane row
    const int koff   = (mat >> 1) << 3;
    const uint32_t aE = (uint32_t)__cvta_generic_to_shared(e_s);
    const uint32_t aH = (uint32_t)__cvta_generic_to_shared(h_s);
    const uint32_t a0E = aE + (uint32_t)((wm * 32 + rowoff) * LDE + koff) * 2;
    const uint32_t a0H = aH + (uint32_t)((wm * 32 + rowoff) * LDH + koff) * 2;
    const uint32_t mstrE = 16 * LDE * 2;
    const uint32_t mstrH = 16 * LDH * 2;
    const int wfrag = (wn * 8) * 32 + lane;        // this warp's B-fragment base offset

    float lj[4] = {0.f, 0.f, 0.f, 0.f};
    float acc[2][8][4];

    for (int layer = 0; layer < NL; layer++) {
        const uint4* wbase = g_wpack + (size_t)(layer * 4) * 8192;

        // ---------- G1s: h_s = relu(e @ Ws1 + bs1) ----------
        gemm64(a0E, mstrE, wbase + wfrag, acc);
        __syncthreads();   // all warps done reading h (prev layer G2t)
        {
            const float* bb_base = bs1 + layer * HH + wn * 64;
            #pragma unroll
            for (int mt = 0; mt < 2; mt++)
                #pragma unroll
                for (int j = 0; j < 8; j++) {
                    int cloc = j * 8 + tg * 2;
                    float2 bb = *reinterpret_cast<const float2*>(bb_base + cloc);
                    int hcol = wn * 64 + cloc;
                    int r0 = wm * 32 + mt * 16 + g;
                    __half2 v0 = __floats2half2_rn(fmaxf(acc[mt][j][0] + bb.x, 0.f),
                                                   fmaxf(acc[mt][j][1] + bb.y, 0.f));
                    __half2 v1 = __floats2half2_rn(fmaxf(acc[mt][j][2] + bb.x, 0.f),
                                                   fmaxf(acc[mt][j][3] + bb.y, 0.f));
                    *reinterpret_cast<__half2*>(h_s + r0 * LDH + hcol)       = v0;
                    *reinterpret_cast<__half2*>(h_s + (r0 + 8) * LDH + hcol) = v1;
                }
        }

        // ---------- G1t: h_t = relu(e @ Wt1 + bt1) (no sync needed in between) ----------
        gemm64(a0E, mstrE, wbase + 2 * 8192 + wfrag, acc);
        {
            const float* bb_base = bt1 + layer * HH + wn * 64;
            #pragma unroll
            for (int mt = 0; mt < 2; mt++)
                #pragma unroll
                for (int j = 0; j < 8; j++) {
                    int cloc = j * 8 + tg * 2;
                    float2 bb = *reinterpret_cast<const float2*>(bb_base + cloc);
                    int hcol = 256 + wn * 64 + cloc;
                    int r0 = wm * 32 + mt * 16 + g;
                    __half2 v0 = __floats2half2_rn(fmaxf(acc[mt][j][0] + bb.x, 0.f),
                                                   fmaxf(acc[mt][j][1] + bb.y, 0.f));
                    __half2 v1 = __floats2half2_rn(fmaxf(acc[mt][j][2] + bb.x, 0.f),
                                                   fmaxf(acc[mt][j][3] + bb.y, 0.f));
                    *reinterpret_cast<__half2*>(h_s + r0 * LDH + hcol)       = v0;
                    *reinterpret_cast<__half2*>(h_s + (r0 + 8) * LDH + hcol) = v1;
                }
        }
        __syncthreads();   // h fully written

        // ---------- G2s: s = tanh(h_s @ Ws2 + bs2) ; o(gmem) *= exp(s) ; lj += s ----------
        gemm64(a0H, mstrH, wbase + 1 * 8192 + wfrag, acc);
        {
            const float* bb_base = bs2 + layer * HALFD + wn * 64;
            #pragma unroll
            for (int mt = 0; mt < 2; mt++)
                #pragma unroll
                for (int j = 0; j < 8; j++) {
                    int cloc = j * 8 + tg * 2;
                    float2 bb = *reinterpret_cast<const float2*>(bb_base + cloc);
                    int r0 = wm * 32 + mt * 16 + g;
                    float* oa_p = out + (size_t)(row0 + r0) * DD + 256 + wn * 64 + cloc;
                    float* ob_p = oa_p + 8 * DD;
                    float2 oa = *reinterpret_cast<float2*>(oa_p);
                    float2 ob = *reinterpret_cast<float2*>(ob_p);
                    float s0 = tanh_acc(acc[mt][j][0] + bb.x);
                    float s1 = tanh_acc(acc[mt][j][1] + bb.y);
                    float s2 = tanh_acc(acc[mt][j][2] + bb.x);
                    float s3 = tanh_acc(acc[mt][j][3] + bb.y);
                    lj[mt * 2]     += s0 + s1;
                    lj[mt * 2 + 1] += s2 + s3;
                    oa.x *= __expf(s0);  oa.y *= __expf(s1);
                    ob.x *= __expf(s2);  ob.y *= __expf(s3);
                    *reinterpret_cast<float2*>(oa_p) = oa;
                    *reinterpret_cast<float2*>(ob_p) = ob;
                }
        }

        // ---------- G2t: t = h_t @ Wt2 + bt2 ; o(gmem) += t ----------
        gemm64(a0H + 512, mstrH, wbase + 3 * 8192 + wfrag, acc);
        {
            const float* bb_base = bt2 + layer * HALFD + wn * 64;
            #pragma unroll
            for (int mt = 0; mt < 2; mt++)
                #pragma unroll
                for (int j = 0; j < 8; j++) {
                    int cloc = j * 8 + tg * 2;
                    float2 bb = *reinterpret_cast<const float2*>(bb_base + cloc);
                    int r0 = wm * 32 + mt * 16 + g;
                    float* oa_p = out + (size_t)(row0 + r0) * DD + 256 + wn * 64 + cloc;
                    float* ob_p = oa_p + 8 * DD;
                    float2 oa = *reinterpret_cast<float2*>(oa_p);
                    float2 ob = *reinterpret_cast<float2*>(ob_p);
                    oa.x += acc[mt][j][0] + bb.x;
                    oa.y += acc[mt][j][1] + bb.y;
                    ob.x += acc[mt][j][2] + bb.x;
                    ob.y += acc[mt][j][3] + bb.y;
                    *reinterpret_cast<float2*>(oa_p) = oa;
                    *reinterpret_cast<float2*>(ob_p) = ob;
                }
        }
        // o is thread-private (same thread owns same (r,c) in G2s/G2t across layers);
        // h protected by the two syncs around its rewrite.
    }

    // ---- deterministic logjac reduction (4 n-warps per row) ----
    #pragma unroll
    for (int k = 0; k < 4; k++) {
        float v = lj[k];
        v += __shfl_down_sync(0xffffffffu, v, 2);
        v += __shfl_down_sync(0xffffffffu, v, 1);
        if (tg == 0) {
            int r = wm * 32 + (k >> 1) * 16 + (k & 1) * 8 + g;
            lj_s[r * 4 + wn] = v;
        }
    }
    __syncthreads();
    if (tid < MT) {
        float v = 0.f;
        #pragma unroll
        for (int j = 0; j < 4; j++) v += lj_s[tid * 4 + j];
        out[(size_t)NROWS * DD + row0 + tid] = v;
    }
}

extern "C" void kernel_launch(void* const* d_in, const int* in_sizes, int n_in,
                              void* d_out, int out_size)
{
    const float* z   = (const float*)d_in[0];
    const float* Ws1 = (const float*)d_in[1];
    const float* bs1 = (const float*)d_in[2];
    const float* Ws2 = (const float*)d_in[3];
    const float* bs2 = (const float*)d_in[4];
    const float* Wt1 = (const float*)d_in[5];
    const float* bt1 = (const float*)d_in[6];
    const float* Wt2 = (const float*)d_in[7];
    const float* bt2 = (const float*)d_in[8];
    float* out = (float*)d_out;

    static bool attr_set = false;
    if (!attr_set) {
        cudaFuncSetAttribute(nvp_main, cudaFuncAttributeMaxDynamicSharedMemorySize, SM_TOT);
        attr_set = true;
    }

    // 1) pack weights: kpair-fused fragment layout (LDG.128)
    pack_w<<<(NL * 4 * 8 * 32 * 32 + 255) / 256, 256>>>(Ws1, Ws2, Wt1, Wt2);

    // 2) fused 8-layer RealNVP: MT=64, o in gmem (L2-resident), 2 CTAs/SM, 2 syncs/layer
    nvp_main<<<NCTAS, THREADS, SM_TOT>>>(z, bs1, bs2, bt1, bt2, out);
}

// round 16
// speedup vs baseline: 2.9578x; 2.9578x over previous
#include <cuda_runtime.h>
#include <cuda_fp16.h>
#include <cstdint>

// Problem constants
#define NROWS 65536
#define DD    512
#define NL    8
#define HH    256
#define HALFD 256

// Tiling: MT=32 rows/CTA, 8 warps along N, 2 CTAs/SM.
// G1 fused: 32x512 (warp tile 32x64); G2: 32x256 (warp tile 32x32).
// o-state lives in REGISTERS (32 per thread). smem = e + h + lj ~= 50KB.
#define MT      32
#define THREADS 256
#define NCTAS   (NROWS / MT)   // 2048
#define LDE     264            // halfs, leading dim of e tile
#define LDH     520            // halfs, leading dim of h tile (512 cols + pad)

// Packed fp16 weights in kstep-major mma-B-fragment order (R1 layout):
// [layer][mat 4][kstep 16][ntile 32][lane 32] as uint2 {b0b1, b2b3}
__device__ uint2 g_wpack[NL * 4 * 16 * 32 * 32];

__global__ void pack_w(const float* __restrict__ Ws1, const float* __restrict__ Ws2,
                       const float* __restrict__ Wt1, const float* __restrict__ Wt2)
{
    int idx = blockIdx.x * blockDim.x + threadIdx.x;
    if (idx >= NL * 4 * 16 * 32 * 32) return;
    int lane  = idx & 31;
    int nt    = (idx >> 5) & 31;
    int ks    = (idx >> 10) & 15;
    int mat   = (idx >> 14) & 3;
    int layer = idx >> 16;
    const float* W = (mat == 0) ? Ws1 : (mat == 1) ? Ws2 : (mat == 2) ? Wt1 : Wt2;
    W += (size_t)layer * HH * HALFD;   // every matrix is 256x256 [K][N] row-major
    int n  = nt * 8 + (lane >> 2);
    int k0 = ks * 16 + (lane & 3) * 2;
    __half2 p0 = __floats2half2_rn(W[k0 * 256 + n],       W[(k0 + 1) * 256 + n]);
    __half2 p1 = __floats2half2_rn(W[(k0 + 8) * 256 + n], W[(k0 + 9) * 256 + n]);
    uint2 v;
    v.x = *reinterpret_cast<uint32_t*>(&p0);
    v.y = *reinterpret_cast<uint32_t*>(&p1);
    g_wpack[idx] = v;
}

__device__ __forceinline__ void mma16816(float c[4], const uint32_t a[4], uint32_t b0, uint32_t b1)
{
    asm volatile(
        "mma.sync.aligned.m16n8k16.row.col.f32.f16.f16.f32 "
        "{%0,%1,%2,%3},{%4,%5,%6,%7},{%8,%9},{%0,%1,%2,%3};\n"
        : "+f"(c[0]), "+f"(c[1]), "+f"(c[2]), "+f"(c[3])
        : "r"(a[0]), "r"(a[1]), "r"(a[2]), "r"(a[3]), "r"(b0), "r"(b1));
}

__device__ __forceinline__ void ldmA(uint32_t a[4], uint32_t addr)
{
    asm volatile(
        "ldmatrix.sync.aligned.m8n8.x4.shared.b16 {%0,%1,%2,%3},[%4];\n"
        : "=r"(a[0]), "=r"(a[1]), "=r"(a[2]), "=r"(a[3])
        : "r"(addr));
}

__device__ __forceinline__ float tanh_acc(float x)
{
    x = fminf(fmaxf(x, -15.f), 15.f);
    float e2 = __expf(2.f * x);
    return __fdividef(e2 - 1.f, e2 + 1.f);
}

// Fused G1: warp tile 32x64 (8 ntiles), B loads chunked 4+4 to cap live registers.
__device__ __forceinline__ void gemm512(uint32_t a0, uint32_t mstride,
                                        const uint2* __restrict__ wlane,
                                        float acc[2][8][4])
{
    #pragma unroll
    for (int mt = 0; mt < 2; mt++)
        #pragma unroll
        for (int j = 0; j < 8; j++)
            #pragma unroll
            for (int q = 0; q < 4; q++) acc[mt][j][q] = 0.f;

    #pragma unroll
    for (int ks = 0; ks < 16; ks++) {
        uint32_t a[2][4];
        ldmA(a[0], a0 + ks * 32);
        ldmA(a[1], a0 + ks * 32 + mstride);
        const uint2* wk = wlane + ks * 1024;
        {
            uint2 b[4];
            #pragma unroll
            for (int j = 0; j < 4; j++) b[j] = wk[j * 32];
            #pragma unroll
            for (int mt = 0; mt < 2; mt++)
                #pragma unroll
                for (int j = 0; j < 4; j++)
                    mma16816(acc[mt][j], a[mt], b[j].x, b[j].y);
        }
        {
            uint2 b[4];
            #pragma unroll
            for (int j = 0; j < 4; j++) b[j] = wk[(j + 4) * 32];
            #pragma unroll
            for (int mt = 0; mt < 2; mt++)
                #pragma unroll
                for (int j = 0; j < 4; j++)
                    mma16816(acc[mt][j + 4], a[mt], b[j].x, b[j].y);
        }
    }
}

// G2: warp tile 32x32 (4 ntiles), double-buffered kstep prefetch (acc only 32 regs).
__device__ __forceinline__ void gemm256(uint32_t a0, uint32_t mstride,
                                        const uint2* __restrict__ wlane,
                                        float acc[2][4][4])
{
    #pragma unroll
    for (int mt = 0; mt < 2; mt++)
        #pragma unroll
        for (int nt = 0; nt < 4; nt++)
            #pragma unroll
            for (int q = 0; q < 4; q++) acc[mt][nt][q] = 0.f;

    uint2 b[4];
    #pragma unroll
    for (int nt = 0; nt < 4; nt++) b[nt] = wlane[nt * 32];

    #pragma unroll
    for (int ks = 0; ks < 16; ks++) {
        uint2 bn[4];
        if (ks < 15) {
            #pragma unroll
            for (int nt = 0; nt < 4; nt++)
                bn[nt] = wlane[(ks + 1) * 1024 + nt * 32];
        }
        uint32_t a[2][4];
        ldmA(a[0], a0 + ks * 32);
        ldmA(a[1], a0 + ks * 32 + mstride);
        #pragma unroll
        for (int mt = 0; mt < 2; mt++)
            #pragma unroll
            for (int nt = 0; nt < 4; nt++)
                mma16816(acc[mt][nt], a[mt], b[nt].x, b[nt].y);
        if (ks < 15) {
            #pragma unroll
            for (int nt = 0; nt < 4; nt++) b[nt] = bn[nt];
        }
    }
}

// SMEM layout (bytes): e + h + lj ~= 50KB -> 2 CTAs/SM with a big L1D carveout
#define SM_E   0
#define SM_H   (MT * LDE * 2)                 // 16896
#define SM_LJ  (SM_H + MT * LDH * 2)          // 50176
#define SM_TOT (SM_LJ + MT * 8 * 4)           // 51200

__global__ void __launch_bounds__(THREADS, 2) nvp_main(
    const float* __restrict__ z,
    const float* __restrict__ bs1, const float* __restrict__ bs2,
    const float* __restrict__ bt1, const float* __restrict__ bt2,
    float* __restrict__ out)
{
    extern __shared__ char smraw[];
    __half* e_s  = reinterpret_cast<__half*>(smraw + SM_E);
    __half* h_s  = reinterpret_cast<__half*>(smraw + SM_H);
    float*  lj_s = reinterpret_cast<float*>(smraw + SM_LJ);

    const int tid  = threadIdx.x;
    const int row0 = blockIdx.x * MT;

    // Load z: even cols -> e (f16 smem) + identity half of out.
    for (int idx = tid; idx < MT * 256; idx += THREADS) {
        int r = idx >> 8, c = idx & 255;
        float2 p = reinterpret_cast<const float2*>(z + (size_t)(row0 + r) * DD)[c];
        e_s[r * LDE + c] = __float2half_rn(p.x);
        out[(size_t)(row0 + r) * DD + c] = p.x;
    }

    const int warp = tid >> 5, lane = tid & 31;
    const int wn = warp;                          // 8 warps along N
    const int g = lane >> 2, tg = lane & 3;
    const int mat = lane >> 3, within = lane & 7;
    const int rowoff = ((mat & 1) << 3) + within; // ldmatrix per-lane row
    const int koff   = (mat >> 1) << 3;
    const uint32_t aE = (uint32_t)__cvta_generic_to_shared(e_s);
    const uint32_t aH = (uint32_t)__cvta_generic_to_shared(h_s);
    const uint32_t a0E = aE + (uint32_t)(rowoff * LDE + koff) * 2;
    const uint32_t a0H = aH + (uint32_t)(rowoff * LDH + koff) * 2;
    const uint32_t mstrE = 16 * LDE * 2;
    const uint32_t mstrH = 16 * LDH * 2;

    // G1 (fused) per-warp selections: warps 0-3 -> Ws1/bs1, warps 4-7 -> Wt1/bt1
    const int g1mat  = (wn >= 4) ? 2 : 0;
    const int g1nt0  = (wn & 3) * 8;
    const float* g1bias = (wn >= 4) ? bt1 : bs1;

    // ---- o-state in registers: o[mt][nt][q] <-> row (mt*16+g [+8 if q>=2]),
    //      col (wn*32+nt*8+tg*2 [+1 if q odd]) ; z col = 2*col+1 ----
    float o[2][4][4];
    #pragma unroll
    for (int mt = 0; mt < 2; mt++)
        #pragma unroll
        for (int nt = 0; nt < 4; nt++) {
            int r0 = mt * 16 + g;
            int c0 = wn * 32 + nt * 8 + tg * 2;
            const float* zr0 = z + (size_t)(row0 + r0) * DD;
            const float* zr1 = z + (size_t)(row0 + r0 + 8) * DD;
            o[mt][nt][0] = __ldg(zr0 + 2 * c0 + 1);
            o[mt][nt][1] = __ldg(zr0 + 2 * c0 + 3);
            o[mt][nt][2] = __ldg(zr1 + 2 * c0 + 1);
            o[mt][nt][3] = __ldg(zr1 + 2 * c0 + 3);
        }
    __syncthreads();

    float lj[4] = {0.f, 0.f, 0.f, 0.f};
    float acc1[2][8][4];
    float acc2[2][4][4];

    for (int layer = 0; layer < NL; layer++) {
        const uint2* wbase = g_wpack + (size_t)(layer * 4) * 16384;

        // ---------- G1 (fused): h[:, wn*64..] = relu(e @ [Ws1|Wt1] + [bs1|bt1]) ----------
        gemm512(a0E, mstrE, wbase + (size_t)g1mat * 16384 + g1nt0 * 32 + lane, acc1);
        __syncthreads();   // all warps done reading h (prev layer G2t)
        {
            const float* bb_base = g1bias + layer * HH + (wn & 3) * 64;
            #pragma unroll
            for (int mt = 0; mt < 2; mt++)
                #pragma unroll
                for (int j = 0; j < 8; j++) {
                    int cloc = j * 8 + tg * 2;
                    float2 bb = *reinterpret_cast<const float2*>(bb_base + cloc);
                    int hcol = wn * 64 + cloc;
                    int r0 = mt * 16 + g;
                    __half2 v0 = __floats2half2_rn(fmaxf(acc1[mt][j][0] + bb.x, 0.f),
                                                   fmaxf(acc1[mt][j][1] + bb.y, 0.f));
                    __half2 v1 = __floats2half2_rn(fmaxf(acc1[mt][j][2] + bb.x, 0.f),
                                                   fmaxf(acc1[mt][j][3] + bb.y, 0.f));
                    *reinterpret_cast<__half2*>(h_s + r0 * LDH + hcol)       = v0;
                    *reinterpret_cast<__half2*>(h_s + (r0 + 8) * LDH + hcol) = v1;
                }
        }
        __syncthreads();   // h fully written

        // ---------- G2s: s = tanh(h_s @ Ws2 + bs2) ; o *= exp(s) ; lj += s ----------
        gemm256(a0H, mstrH, wbase + (size_t)1 * 16384 + (wn * 4) * 32 + lane, acc2);
        #pragma unroll
        for (int mt = 0; mt < 2; mt++)
            #pragma unroll
            for (int nt = 0; nt < 4; nt++) {
                int col0 = wn * 32 + nt * 8 + tg * 2;
                float2 bb = *reinterpret_cast<const float2*>(bs2 + layer * HALFD + col0);
                float s0 = tanh_acc(acc2[mt][nt][0] + bb.x);
                float s1 = tanh_acc(acc2[mt][nt][1] + bb.y);
                float s2 = tanh_acc(acc2[mt][nt][2] + bb.x);
                float s3 = tanh_acc(acc2[mt][nt][3] + bb.y);
                lj[mt * 2]     += s0 + s1;
                lj[mt * 2 + 1] += s2 + s3;
                o[mt][nt][0] *= __expf(s0);
                o[mt][nt][1] *= __expf(s1);
                o[mt][nt][2] *= __expf(s2);
                o[mt][nt][3] *= __expf(s3);
            }

        // ---------- G2t: t = h_t @ Wt2 + bt2 ; o += t ----------
        gemm256(a0H + 512, mstrH, wbase + (size_t)3 * 16384 + (wn * 4) * 32 + lane, acc2);
        #pragma unroll
        for (int mt = 0; mt < 2; mt++)
            #pragma unroll
            for (int nt = 0; nt < 4; nt++) {
                int col0 = wn * 32 + nt * 8 + tg * 2;
                float2 bb = *reinterpret_cast<const float2*>(bt2 + layer * HALFD + col0);
                o[mt][nt][0] += acc2[mt][nt][0] + bb.x;
                o[mt][nt][1] += acc2[mt][nt][1] + bb.y;
                o[mt][nt][2] += acc2[mt][nt][2] + bb.x;
                o[mt][nt][3] += acc2[mt][nt][3] + bb.y;
            }
        // o is thread-private registers; h protected by the two syncs around its rewrite
    }

    // ---- odd half of output from o registers (float2 stores, coalesced per quad) ----
    #pragma unroll
    for (int mt = 0; mt < 2; mt++)
        #pragma unroll
        for (int nt = 0; nt < 4; nt++) {
            int r0 = mt * 16 + g;
            int c0 = wn * 32 + nt * 8 + tg * 2;
            *reinterpret_cast<float2*>(out + (size_t)(row0 + r0) * DD + 256 + c0)
                = make_float2(o[mt][nt][0], o[mt][nt][1]);
            *reinterpret_cast<float2*>(out + (size_t)(row0 + r0 + 8) * DD + 256 + c0)
                = make_float2(o[mt][nt][2], o[mt][nt][3]);
        }

    // ---- deterministic logjac reduction ----
    #pragma unroll
    for (int k = 0; k < 4; k++) {
        float v = lj[k];
        v += __shfl_down_sync(0xffffffffu, v, 2);
        v += __shfl_down_sync(0xffffffffu, v, 1);
        if (tg == 0) {
            int r = (k >> 1) * 16 + (k & 1) * 8 + g;
            lj_s[r * 8 + wn] = v;
        }
    }
    __syncthreads();
    if (tid < MT) {
        float v = 0.f;
        #pragma unroll
        for (int j = 0; j < 8; j++) v += lj_s[tid * 8 + j];
        out[(size_t)NROWS * DD + row0 + tid] = v;
    }
}

extern "C" void kernel_launch(void* const* d_in, const int* in_sizes, int n_in,
                              void* d_out, int out_size)
{
    const float* z   = (const float*)d_in[0];
    const float* Ws1 = (const float*)d_in[1];
    const float* bs1 = (const float*)d_in[2];
    const float* Ws2 = (const float*)d_in[3];
    const float* bs2 = (const float*)d_in[4];
    const float* Wt1 = (const float*)d_in[5];
    const float* bt1 = (const float*)d_in[6];
    const float* Wt2 = (const float*)d_in[7];
    const float* bt2 = (const float*)d_in[8];
    float* out = (float*)d_out;

    static bool attr_set = false;
    if (!attr_set) {
        cudaFuncSetAttribute(nvp_main, cudaFuncAttributeMaxDynamicSharedMemorySize, SM_TOT);
        attr_set = true;
    }

    // 1) pack weights to fragment-native fp16 (kstep-major uint2 layout)
    pack_w<<<(NL * 4 * 16 * 32 * 32 + 255) / 256, 256>>>(Ws1, Ws2, Wt1, Wt2);

    // 2) fused 8-layer RealNVP: MT=32, fused G1, o in registers, 2 CTAs/SM, 2 syncs/layer
    nvp_main<<<NCTAS, THREADS, SM_TOT>>>(z, bs1, bs2, bt1, bt2, out);
}

// round 17
// speedup vs baseline: 3.3475x; 1.1318x over previous
#include <cuda_runtime.h>
#include <cuda_fp16.h>
#include <cstdint>

// Problem constants
#define NROWS 65536
#define DD    512
#define NL    8
#define HH    256
#define HALFD 256

// Tiling: MT=32 rows/CTA, 8 warps along N, 2 CTAs/SM.
// G1 fused: 32x512 output (warp tile 32x64); G2 pair fused: two 32x256 GEMMs in one loop.
#define MT      32
#define THREADS 256
#define NCTAS   (NROWS / MT)   // 2048
#define LDE     264            // halfs, leading dim of e tile
#define LDH     520            // halfs, leading dim of h tile (512 cols + pad)
#define LDO     260            // floats, leading dim of o tile

// Packed fp16 weights, kpair-fused mma-B-fragment order:
// [layer][mat 4][kpair 8][ntile 32][lane 32] as uint4:
//   .x,.y = kstep 2*kp fragments ; .z,.w = kstep 2*kp+1 fragments
__device__ uint4 g_wpack[NL * 4 * 8 * 32 * 32];

__global__ void pack_w(const float* __restrict__ Ws1, const float* __restrict__ Ws2,
                       const float* __restrict__ Wt1, const float* __restrict__ Wt2)
{
    int idx = blockIdx.x * blockDim.x + threadIdx.x;
    if (idx >= NL * 4 * 8 * 32 * 32) return;
    int lane  = idx & 31;
    int nt    = (idx >> 5) & 31;
    int kp    = (idx >> 10) & 7;
    int mat   = (idx >> 13) & 3;
    int layer = idx >> 15;
    const float* W = (mat == 0) ? Ws1 : (mat == 1) ? Ws2 : (mat == 2) ? Wt1 : Wt2;
    W += (size_t)layer * HH * HALFD;   // every matrix is 256x256 [K][N] row-major
    int n  = nt * 8 + (lane >> 2);
    int k0 = kp * 32 + (lane & 3) * 2;
    __half2 p0 = __floats2half2_rn(W[(k0     ) * 256 + n], W[(k0 +  1) * 256 + n]);
    __half2 p1 = __floats2half2_rn(W[(k0 +  8) * 256 + n], W[(k0 +  9) * 256 + n]);
    __half2 p2 = __floats2half2_rn(W[(k0 + 16) * 256 + n], W[(k0 + 17) * 256 + n]);
    __half2 p3 = __floats2half2_rn(W[(k0 + 24) * 256 + n], W[(k0 + 25) * 256 + n]);
    uint4 v;
    v.x = *reinterpret_cast<uint32_t*>(&p0);
    v.y = *reinterpret_cast<uint32_t*>(&p1);
    v.z = *reinterpret_cast<uint32_t*>(&p2);
    v.w = *reinterpret_cast<uint32_t*>(&p3);
    g_wpack[idx] = v;
}

__device__ __forceinline__ void mma16816(float c[4], const uint32_t a[4], uint32_t b0, uint32_t b1)
{
    asm volatile(
        "mma.sync.aligned.m16n8k16.row.col.f32.f16.f16.f32 "
        "{%0,%1,%2,%3},{%4,%5,%6,%7},{%8,%9},{%0,%1,%2,%3};\n"
        : "+f"(c[0]), "+f"(c[1]), "+f"(c[2]), "+f"(c[3])
        : "r"(a[0]), "r"(a[1]), "r"(a[2]), "r"(a[3]), "r"(b0), "r"(b1));
}

__device__ __forceinline__ void ldmA(uint32_t a[4], uint32_t addr)
{
    asm volatile(
        "ldmatrix.sync.aligned.m8n8.x4.shared.b16 {%0,%1,%2,%3},[%4];\n"
        : "=r"(a[0]), "=r"(a[1]), "=r"(a[2]), "=r"(a[3])
        : "r"(addr));
}

__device__ __forceinline__ float tanh_acc(float x)
{
    x = fminf(fmaxf(x, -15.f), 15.f);
    float e2 = __expf(2.f * x);
    return __fdividef(e2 - 1.f, e2 + 1.f);
}

// e^s for s in (-1,1): degree-8 Taylor on the FMA pipe (rel err ~7.5e-6); avoids MUFU.
__device__ __forceinline__ float exp_poly(float s)
{
    float p = 2.4801587e-5f;              // 1/8!
    p = fmaf(p, s, 1.9841270e-4f);        // 1/7!
    p = fmaf(p, s, 1.3888889e-3f);        // 1/6!
    p = fmaf(p, s, 8.3333333e-3f);        // 1/5!
    p = fmaf(p, s, 4.1666667e-2f);        // 1/4!
    p = fmaf(p, s, 1.6666667e-1f);        // 1/3!
    p = fmaf(p, s, 0.5f);
    p = fmaf(p, s, 1.0f);
    p = fmaf(p, s, 1.0f);
    return p;
}

// Fused G1: warp tile 32x64 (8 ntiles), B = one kpair (8 uint4) loaded per 2 ksteps.
__device__ __forceinline__ void gemm512(uint32_t a0, uint32_t mstride,
                                        const uint4* __restrict__ wlane,
                                        float acc[2][8][4])
{
    #pragma unroll
    for (int mt = 0; mt < 2; mt++)
        #pragma unroll
        for (int j = 0; j < 8; j++)
            #pragma unroll
            for (int q = 0; q < 4; q++) acc[mt][j][q] = 0.f;

    #pragma unroll
    for (int kp = 0; kp < 8; kp++) {
        uint4 b[8];
        #pragma unroll
        for (int j = 0; j < 8; j++) b[j] = wlane[kp * 1024 + j * 32];
        uint32_t a[2][4];
        ldmA(a[0], a0 + (2 * kp) * 32);
        ldmA(a[1], a0 + (2 * kp) * 32 + mstride);
        #pragma unroll
        for (int mt = 0; mt < 2; mt++)
            #pragma unroll
            for (int j = 0; j < 8; j++)
                mma16816(acc[mt][j], a[mt], b[j].x, b[j].y);
        ldmA(a[0], a0 + (2 * kp + 1) * 32);
        ldmA(a[1], a0 + (2 * kp + 1) * 32 + mstride);
        #pragma unroll
        for (int mt = 0; mt < 2; mt++)
            #pragma unroll
            for (int j = 0; j < 8; j++)
                mma16816(acc[mt][j], a[mt], b[j].z, b[j].w);
    }
}

// Fused G2 pair: two independent 32x256 GEMMs (A = h_s and h_t halves) in one loop.
// Double the independent MMA work per load window -> better latency hiding.
__device__ __forceinline__ void gemm256pair(uint32_t a0s, uint32_t a0t, uint32_t mstride,
                                            const uint4* __restrict__ wS,
                                            const uint4* __restrict__ wT,
                                            float accS[2][4][4], float accT[2][4][4])
{
    #pragma unroll
    for (int mt = 0; mt < 2; mt++)
        #pragma unroll
        for (int nt = 0; nt < 4; nt++)
            #pragma unroll
            for (int q = 0; q < 4; q++) { accS[mt][nt][q] = 0.f; accT[mt][nt][q] = 0.f; }

    #pragma unroll
    for (int kp = 0; kp < 8; kp++) {
        uint4 bS[4], bT[4];
        #pragma unroll
        for (int nt = 0; nt < 4; nt++) {
            bS[nt] = wS[kp * 1024 + nt * 32];
            bT[nt] = wT[kp * 1024 + nt * 32];
        }
        // kstep even = 2*kp
        {
            uint32_t a[2][4];
            ldmA(a[0], a0s + (2 * kp) * 32);
            ldmA(a[1], a0s + (2 * kp) * 32 + mstride);
            #pragma unroll
            for (int mt = 0; mt < 2; mt++)
                #pragma unroll
                for (int nt = 0; nt < 4; nt++)
                    mma16816(accS[mt][nt], a[mt], bS[nt].x, bS[nt].y);
            ldmA(a[0], a0t + (2 * kp) * 32);
            ldmA(a[1], a0t + (2 * kp) * 32 + mstride);
            #pragma unroll
            for (int mt = 0; mt < 2; mt++)
                #pragma unroll
                for (int nt = 0; nt < 4; nt++)
                    mma16816(accT[mt][nt], a[mt], bT[nt].x, bT[nt].y);
        }
        // kstep odd = 2*kp+1
        {
            uint32_t a[2][4];
            ldmA(a[0], a0s + (2 * kp + 1) * 32);
            ldmA(a[1], a0s + (2 * kp + 1) * 32 + mstride);
            #pragma unroll
            for (int mt = 0; mt < 2; mt++)
                #pragma unroll
                for (int nt = 0; nt < 4; nt++)
                    mma16816(accS[mt][nt], a[mt], bS[nt].z, bS[nt].w);
            ldmA(a[0], a0t + (2 * kp + 1) * 32);
            ldmA(a[1], a0t + (2 * kp + 1) * 32 + mstride);
            #pragma unroll
            for (int mt = 0; mt < 2; mt++)
                #pragma unroll
                for (int nt = 0; nt < 4; nt++)
                    mma16816(accT[mt][nt], a[mt], bT[nt].z, bT[nt].w);
        }
    }
}

// SMEM layout (bytes) -- ~84.5KB/CTA -> 2 CTAs per SM
#define SM_E   0
#define SM_H   (MT * LDE * 2)                 // 16896
#define SM_O   (SM_H + MT * LDH * 2)          // 50176
#define SM_LJ  (SM_O + MT * LDO * 4)          // 83456
#define SM_TOT (SM_LJ + MT * 8 * 4)           // 84480

__global__ void __launch_bounds__(THREADS, 2) nvp_main(
    const float* __restrict__ z,
    const float* __restrict__ bs1, const float* __restrict__ bs2,
    const float* __restrict__ bt1, const float* __restrict__ bt2,
    float* __restrict__ out)
{
    extern __shared__ char smraw[];
    __half* e_s  = reinterpret_cast<__half*>(smraw + SM_E);
    __half* h_s  = reinterpret_cast<__half*>(smraw + SM_H);
    float*  o_s  = reinterpret_cast<float*>(smraw + SM_O);
    float*  lj_s = reinterpret_cast<float*>(smraw + SM_LJ);

    const int tid  = threadIdx.x;
    const int row0 = blockIdx.x * MT;

    // Load: z row -> (e f16 smem, o f32 smem); even half of output is the identity copy.
    for (int idx = tid; idx < MT * 256; idx += THREADS) {
        int r = idx >> 8, c = idx & 255;
        float2 p = reinterpret_cast<const float2*>(z + (size_t)(row0 + r) * DD)[c];
        e_s[r * LDE + c] = __float2half_rn(p.x);
        o_s[r * LDO + c] = p.y;
        out[(size_t)(row0 + r) * DD + c] = p.x;
    }
    __syncthreads();

    const int warp = tid >> 5, lane = tid & 31;
    const int wn = warp;                          // 8 warps along N
    const int g = lane >> 2, tg = lane & 3;
    const int mat = lane >> 3, within = lane & 7;
    const int rowoff = ((mat & 1) << 3) + within; // ldmatrix per-lane row
    const int koff   = (mat >> 1) << 3;
    const uint32_t aE = (uint32_t)__cvta_generic_to_shared(e_s);
    const uint32_t aH = (uint32_t)__cvta_generic_to_shared(h_s);
    const uint32_t a0E = aE + (uint32_t)(rowoff * LDE + koff) * 2;
    const uint32_t a0H = aH + (uint32_t)(rowoff * LDH + koff) * 2;
    const uint32_t mstrE = 16 * LDE * 2;
    const uint32_t mstrH = 16 * LDH * 2;

    // G1 (fused) per-warp selections: warps 0-3 -> Ws1/bs1, warps 4-7 -> Wt1/bt1
    const int g1mat  = (wn >= 4) ? 2 : 0;
    const int g1nt0  = (wn & 3) * 8;
    const float* g1bias = (wn >= 4) ? bt1 : bs1;

    float lj[4] = {0.f, 0.f, 0.f, 0.f};
    float acc1[2][8][4];

    for (int layer = 0; layer < NL; layer++) {
        const uint4* wbase = g_wpack + (size_t)(layer * 4) * 8192;

        // ---------- G1 (fused): h[:, wn*64..] = relu(e @ [Ws1|Wt1] + [bs1|bt1]) ----------
        gemm512(a0E, mstrE, wbase + (size_t)g1mat * 8192 + g1nt0 * 32 + lane, acc1);
        __syncthreads();   // all warps done reading h (prev layer G2 pair)
        {
            const float* bb_base = g1bias + layer * HH + (wn & 3) * 64;
            #pragma unroll
            for (int mt = 0; mt < 2; mt++)
                #pragma unroll
                for (int j = 0; j < 8; j++) {
                    int cloc = j * 8 + tg * 2;
                    float2 bb = *reinterpret_cast<const float2*>(bb_base + cloc);
                    int hcol = wn * 64 + cloc;
                    int r0 = mt * 16 + g;
                    __half2 v0 = __floats2half2_rn(fmaxf(acc1[mt][j][0] + bb.x, 0.f),
                                                   fmaxf(acc1[mt][j][1] + bb.y, 0.f));
                    __half2 v1 = __floats2half2_rn(fmaxf(acc1[mt][j][2] + bb.x, 0.f),
                                                   fmaxf(acc1[mt][j][3] + bb.y, 0.f));
                    *reinterpret_cast<__half2*>(h_s + r0 * LDH + hcol)       = v0;
                    *reinterpret_cast<__half2*>(h_s + (r0 + 8) * LDH + hcol) = v1;
                }
        }
        __syncthreads();   // h fully written

        // ---------- G2 pair: s-GEMM (h_s @ Ws2) and t-GEMM (h_t @ Wt2) together ----------
        {
            float accS[2][4][4], accT[2][4][4];
            gemm256pair(a0H, a0H + 512, mstrH,
                        wbase + (size_t)1 * 8192 + (wn * 4) * 32 + lane,
                        wbase + (size_t)3 * 8192 + (wn * 4) * 32 + lane,
                        accS, accT);
            // fused epilogue: s = tanh(yS + bs2); lj += s; o = exp(s)*o + yT + bt2
            #pragma unroll
            for (int mt = 0; mt < 2; mt++)
                #pragma unroll
                for (int nt = 0; nt < 4; nt++) {
                    int col0 = wn * 32 + nt * 8 + tg * 2;
                    float2 bbs = *reinterpret_cast<const float2*>(bs2 + layer * HALFD + col0);
                    float2 bbt = *reinterpret_cast<const float2*>(bt2 + layer * HALFD + col0);
                    int r0 = mt * 16 + g;
                    float s0 = tanh_acc(accS[mt][nt][0] + bbs.x);
                    float s1 = tanh_acc(accS[mt][nt][1] + bbs.y);
                    float s2 = tanh_acc(accS[mt][nt][2] + bbs.x);
                    float s3 = tanh_acc(accS[mt][nt][3] + bbs.y);
                    lj[mt * 2]     += s0 + s1;
                    lj[mt * 2 + 1] += s2 + s3;
                    float2 oa = *reinterpret_cast<float2*>(o_s + r0 * LDO + col0);
                    float2 ob = *reinterpret_cast<float2*>(o_s + (r0 + 8) * LDO + col0);
                    oa.x = fmaf(exp_poly(s0), oa.x, accT[mt][nt][0] + bbt.x);
                    oa.y = fmaf(exp_poly(s1), oa.y, accT[mt][nt][1] + bbt.y);
                    ob.x = fmaf(exp_poly(s2), ob.x, accT[mt][nt][2] + bbt.x);
                    ob.y = fmaf(exp_poly(s3), ob.y, accT[mt][nt][3] + bbt.y);
                    *reinterpret_cast<float2*>(o_s + r0 * LDO + col0)       = oa;
                    *reinterpret_cast<float2*>(o_s + (r0 + 8) * LDO + col0) = ob;
                }
        }
        // o positions are thread-private; h protected by the two syncs around its rewrite
    }
    __syncthreads();

    // Odd half of output
    for (int idx = tid; idx < MT * 256; idx += THREADS) {
        int r = idx >> 8, c = idx & 255;
        out[(size_t)(row0 + r) * DD + 256 + c] = o_s[r * LDO + c];
    }

    // Deterministic logjac reduction: intra-warp over tg, then across the 8 n-warps.
    #pragma unroll
    for (int k = 0; k < 4; k++) {
        float v = lj[k];
        v += __shfl_down_sync(0xffffffffu, v, 2);
        v += __shfl_down_sync(0xffffffffu, v, 1);
        if (tg == 0) {
            int r = (k >> 1) * 16 + (k & 1) * 8 + g;
            lj_s[r * 8 + wn] = v;
        }
    }
    __syncthreads();
    if (tid < MT) {
        float v = 0.f;
        #pragma unroll
        for (int j = 0; j < 8; j++) v += lj_s[tid * 8 + j];
        out[(size_t)NROWS * DD + row0 + tid] = v;
    }
}

extern "C" void kernel_launch(void* const* d_in, const int* in_sizes, int n_in,
                              void* d_out, int out_size)
{
    const float* z   = (const float*)d_in[0];
    const float* Ws1 = (const float*)d_in[1];
    const float* bs1 = (const float*)d_in[2];
    const float* Ws2 = (const float*)d_in[3];
    const float* bs2 = (const float*)d_in[4];
    const float* Wt1 = (const float*)d_in[5];
    const float* bt1 = (const float*)d_in[6];
    const float* Wt2 = (const float*)d_in[7];
    const float* bt2 = (const float*)d_in[8];
    float* out = (float*)d_out;

    static bool attr_set = false;
    if (!attr_set) {
        cudaFuncSetAttribute(nvp_main, cudaFuncAttributeMaxDynamicSharedMemorySize, SM_TOT);
        attr_set = true;
    }

    // 1) pack weights: kpair-fused fragment layout (LDG.128)
    pack_w<<<(NL * 4 * 8 * 32 * 32 + 255) / 256, 256>>>(Ws1, Ws2, Wt1, Wt2);

    // 2) fused 8-layer RealNVP: fused G1 + fused G2 pair, 2 CTAs/SM, 2 syncs/layer
    nvp_main<<<NCTAS, THREADS, SM_TOT>>>(z, bs1, bs2, bt1, bt2, out);
}